// round 10
// baseline (speedup 1.0000x reference)
#include <cuda_runtime.h>
#include <cuda_bf16.h>
#include <cstdint>

#define INPUT_DIM 16384
#define EMB 1024
#define BATCH 4096
#define XS_SLOTS (INPUT_DIM + EMB)   // 17408 float2 slots, pad-2 bound (<32768, fits 15 bits)

// ---------------- device scratch ----------------
__device__ unsigned short g_comb[INPUT_DIM];                 // e | (neg<<15) per feature j
__device__ __align__(16) unsigned short g_pos[INPUT_DIM];    // slot | (neg<<15), by j
__device__ int g_astart[EMB];                                // pad-2 bucket start slot
__device__ int g_len[EMB];                                   // actual bucket length

// ---------------- K1: extract (bucket, sign) — batched prefetch, 2 rounds max ----------------
__global__ void k_extract(const float* __restrict__ hp) {
    int warp = (blockIdx.x * blockDim.x + threadIdx.x) >> 5;
    int lane = threadIdx.x & 31;
    if (warp >= INPUT_DIM) return;

    const float4* row = reinterpret_cast<const float4*>(hp + (size_t)warp * EMB);
    float4 c[4];
    int my_e = 0; unsigned my_neg = 0; bool has = false;

#pragma unroll
    for (int i = 0; i < 4; i++) c[i] = row[lane + i * 32];
#pragma unroll
    for (int i = 0; i < 4; i++) {
        int base = (lane + i * 32) * 4;
        if (c[i].x != 0.0f) { my_e = base + 0; my_neg = (c[i].x < 0.0f); has = true; }
        if (c[i].y != 0.0f) { my_e = base + 1; my_neg = (c[i].y < 0.0f); has = true; }
        if (c[i].z != 0.0f) { my_e = base + 2; my_neg = (c[i].z < 0.0f); has = true; }
        if (c[i].w != 0.0f) { my_e = base + 3; my_neg = (c[i].w < 0.0f); has = true; }
    }
    unsigned mask = __ballot_sync(0xffffffffu, has);

    if (mask == 0) {
#pragma unroll
        for (int i = 0; i < 4; i++) c[i] = row[lane + (i + 4) * 32];
#pragma unroll
        for (int i = 0; i < 4; i++) {
            int base = (lane + (i + 4) * 32) * 4;
            if (c[i].x != 0.0f) { my_e = base + 0; my_neg = (c[i].x < 0.0f); has = true; }
            if (c[i].y != 0.0f) { my_e = base + 1; my_neg = (c[i].y < 0.0f); has = true; }
            if (c[i].z != 0.0f) { my_e = base + 2; my_neg = (c[i].z < 0.0f); has = true; }
            if (c[i].w != 0.0f) { my_e = base + 3; my_neg = (c[i].w < 0.0f); has = true; }
        }
        mask = __ballot_sync(0xffffffffu, has);
    }

    if (mask == 0) { if (lane == 0) g_comb[warp] = 0; return; }
    int src = __ffs(mask) - 1;
    int e        = __shfl_sync(0xffffffffu, my_e, src);
    unsigned neg = __shfl_sync(0xffffffffu, my_neg, src);
    if (lane == 0) g_comb[warp] = (unsigned short)(e | (neg << 15));
}

// ---------------- K2: fused build — histogram, shuffle-scan (pad-2 slots), slot assign ----------------
__global__ __launch_bounds__(EMB, 1)
void k_build() {
    __shared__ int hist[EMB];
    __shared__ int cur[EMB];
    __shared__ int wsum[32];
    int t = threadIdx.x;
    int lane = t & 31, w = t >> 5;

    hist[t] = 0;
    __syncthreads();

#pragma unroll
    for (int i = 0; i < INPUT_DIM / EMB; i++)
        atomicAdd(&hist[g_comb[i * EMB + t] & (EMB - 1)], 1);
    __syncthreads();

    int c  = hist[t];
    int pl = (c + 1) & ~1;                 // pad to 2 slots (16B float2-pair alignment)

    int v = pl;
#pragma unroll
    for (int off = 1; off < 32; off <<= 1) {
        int n = __shfl_up_sync(0xffffffffu, v, off);
        if (lane >= off) v += n;
    }
    if (lane == 31) wsum[w] = v;
    __syncthreads();
    if (w == 0) {
        int s = wsum[lane];
#pragma unroll
        for (int off = 1; off < 32; off <<= 1) {
            int n = __shfl_up_sync(0xffffffffu, s, off);
            if (lane >= off) s += n;
        }
        wsum[lane] = s;
    }
    __syncthreads();
    int incl  = v + (w > 0 ? wsum[w - 1] : 0);
    int start = incl - pl;
    g_astart[t] = start;
    g_len[t]    = c;
    cur[t]      = start;
    __syncthreads();

#pragma unroll
    for (int i = 0; i < INPUT_DIM / EMB; i++) {
        int j = i * EMB + t;
        unsigned cb = g_comb[j];
        int pos = atomicAdd(&cur[cb & (EMB - 1)], 1);
        g_pos[j] = (unsigned short)(pos | (cb & 0x8000u));
    }
}

// ---------------- K3: main kernel — 2 rows/CTA, float2-interleaved scatter, f4 pair reduce ----------------
#define GTHREADS 1024
__global__ __launch_bounds__(GTHREADS, 1)
void k_gather(const float* __restrict__ x, float* __restrict__ out) {
    extern __shared__ float2 xs2[];        // [XS_SLOTS] slot k = {row0[j], row1[j]}

    int b0 = blockIdx.x * 2;               // rows b0, b0+1
    int t  = threadIdx.x;

    // hoisted metadata: thread t owns bucket t
    int s0 = __ldg(&g_astart[t]);
    int l  = __ldg(&g_len[t]);

    // Phase A: zero the (<=1) pad slot of odd-length buckets
    if (l & 1) xs2[s0 + l] = make_float2(0.0f, 0.0f);

    // Phase B: coalesced 2-row load + permuted, sign-applied float2 scatter
    {
        const float4* gx0 = reinterpret_cast<const float4*>(x + (size_t)b0 * INPUT_DIM);
        const float4* gx1 = reinterpret_cast<const float4*>(x + (size_t)(b0 + 1) * INPUT_DIM);
        const uint2*  gp  = reinterpret_cast<const uint2*>(g_pos);
#pragma unroll
        for (int i = t; i < INPUT_DIM / 4; i += GTHREADS) {
            float4 v0 = gx0[i];
            float4 v1 = gx1[i];
            uint2  p  = gp[i];
            unsigned q0 = p.x & 0xFFFFu, q1 = p.x >> 16;
            unsigned q2 = p.y & 0xFFFFu, q3 = p.y >> 16;
            unsigned s;
            s = (q0 & 0x8000u) << 16;
            xs2[q0 & 0x7FFFu] = make_float2(__uint_as_float(__float_as_uint(v0.x) ^ s),
                                            __uint_as_float(__float_as_uint(v1.x) ^ s));
            s = (q1 & 0x8000u) << 16;
            xs2[q1 & 0x7FFFu] = make_float2(__uint_as_float(__float_as_uint(v0.y) ^ s),
                                            __uint_as_float(__float_as_uint(v1.y) ^ s));
            s = (q2 & 0x8000u) << 16;
            xs2[q2 & 0x7FFFu] = make_float2(__uint_as_float(__float_as_uint(v0.z) ^ s),
                                            __uint_as_float(__float_as_uint(v1.z) ^ s));
            s = (q3 & 0x8000u) << 16;
            xs2[q3 & 0x7FFFu] = make_float2(__uint_as_float(__float_as_uint(v0.w) ^ s),
                                            __uint_as_float(__float_as_uint(v1.w) ^ s));
        }
    }
    __syncthreads();

    // Phase C: float4 = 2 slots = both rows x 2 features; dual accumulators
    {
        const float4* xs4 = reinterpret_cast<const float4*>(xs2) + (s0 >> 1);
        int n4 = ((l + 1) & ~1) >> 1;      // padded slot pairs
        float acc0 = 0.0f, acc1 = 0.0f;
        for (int i = 0; i < n4; i++) {
            float4 v = xs4[i];             // {r0[k], r1[k], r0[k+1], r1[k+1]}
            acc0 += v.x + v.z;
            acc1 += v.y + v.w;
        }
        out[(size_t)b0 * EMB + t]       = acc0;
        out[(size_t)(b0 + 1) * EMB + t] = acc1;
    }
}

extern "C" void kernel_launch(void* const* d_in, const int* in_sizes, int n_in,
                              void* d_out, int out_size) {
    const float* x  = (const float*)d_in[0];   // [BATCH, INPUT_DIM]
    const float* hp = (const float*)d_in[1];   // [INPUT_DIM, EMB]
    float* out = (float*)d_out;                // [BATCH, EMB]

    int smem = XS_SLOTS * (int)sizeof(float2); // 139264 B -> 1 block/SM, 1024 thr
    cudaFuncSetAttribute(k_gather, cudaFuncAttributeMaxDynamicSharedMemorySize, smem);

    k_extract<<<(INPUT_DIM * 32) / 256, 256>>>(hp);
    k_build<<<1, EMB>>>();
    k_gather<<<BATCH / 2, GTHREADS, smem>>>(x, out);
}

// round 11
// speedup vs baseline: 1.1292x; 1.1292x over previous
#include <cuda_runtime.h>
#include <cuda_bf16.h>
#include <cstdint>

#define INPUT_DIM 16384
#define EMB 1024
#define BATCH 4096
#define XS_N (INPUT_DIM + EMB * 3)   // 19456 floats, pad-4 bound (<32768, fits 15 bits)

// ---------------- device scratch ----------------
__device__ unsigned short g_comb[INPUT_DIM];                 // e | (neg<<15) per feature j
__device__ __align__(16) unsigned short g_pos[INPUT_DIM];    // slot | (neg<<15), by j
__device__ int g_astart[EMB];                                // pad-4 bucket start
__device__ int g_len[EMB];                                   // actual bucket length

// ---------------- K1: extract (bucket, sign) — batched prefetch, 2 rounds max ----------------
__global__ void k_extract(const float* __restrict__ hp) {
    int warp = (blockIdx.x * blockDim.x + threadIdx.x) >> 5;
    int lane = threadIdx.x & 31;
    if (warp >= INPUT_DIM) return;

    const float4* row = reinterpret_cast<const float4*>(hp + (size_t)warp * EMB);
    float4 c[4];
    int my_e = 0; unsigned my_neg = 0; bool has = false;

#pragma unroll
    for (int i = 0; i < 4; i++) c[i] = row[lane + i * 32];
#pragma unroll
    for (int i = 0; i < 4; i++) {
        int base = (lane + i * 32) * 4;
        if (c[i].x != 0.0f) { my_e = base + 0; my_neg = (c[i].x < 0.0f); has = true; }
        if (c[i].y != 0.0f) { my_e = base + 1; my_neg = (c[i].y < 0.0f); has = true; }
        if (c[i].z != 0.0f) { my_e = base + 2; my_neg = (c[i].z < 0.0f); has = true; }
        if (c[i].w != 0.0f) { my_e = base + 3; my_neg = (c[i].w < 0.0f); has = true; }
    }
    unsigned mask = __ballot_sync(0xffffffffu, has);

    if (mask == 0) {
#pragma unroll
        for (int i = 0; i < 4; i++) c[i] = row[lane + (i + 4) * 32];
#pragma unroll
        for (int i = 0; i < 4; i++) {
            int base = (lane + (i + 4) * 32) * 4;
            if (c[i].x != 0.0f) { my_e = base + 0; my_neg = (c[i].x < 0.0f); has = true; }
            if (c[i].y != 0.0f) { my_e = base + 1; my_neg = (c[i].y < 0.0f); has = true; }
            if (c[i].z != 0.0f) { my_e = base + 2; my_neg = (c[i].z < 0.0f); has = true; }
            if (c[i].w != 0.0f) { my_e = base + 3; my_neg = (c[i].w < 0.0f); has = true; }
        }
        mask = __ballot_sync(0xffffffffu, has);
    }

    if (mask == 0) { if (lane == 0) g_comb[warp] = 0; return; }
    int src = __ffs(mask) - 1;
    int e        = __shfl_sync(0xffffffffu, my_e, src);
    unsigned neg = __shfl_sync(0xffffffffu, my_neg, src);
    if (lane == 0) g_comb[warp] = (unsigned short)(e | (neg << 15));
}

// ---------------- K2: fused build — histogram, shuffle-scan, slot assign ----------------
__global__ __launch_bounds__(EMB, 1)
void k_build() {
    __shared__ int hist[EMB];
    __shared__ int cur[EMB];
    __shared__ int wsum[32];
    int t = threadIdx.x;
    int lane = t & 31, w = t >> 5;

    hist[t] = 0;
    __syncthreads();

#pragma unroll
    for (int i = 0; i < INPUT_DIM / EMB; i++)
        atomicAdd(&hist[g_comb[i * EMB + t] & (EMB - 1)], 1);
    __syncthreads();

    int c  = hist[t];
    int pl = (c + 3) & ~3;                 // pad to multiple of 4

    int v = pl;
#pragma unroll
    for (int off = 1; off < 32; off <<= 1) {
        int n = __shfl_up_sync(0xffffffffu, v, off);
        if (lane >= off) v += n;
    }
    if (lane == 31) wsum[w] = v;
    __syncthreads();
    if (w == 0) {
        int s = wsum[lane];
#pragma unroll
        for (int off = 1; off < 32; off <<= 1) {
            int n = __shfl_up_sync(0xffffffffu, s, off);
            if (lane >= off) s += n;
        }
        wsum[lane] = s;
    }
    __syncthreads();
    int incl  = v + (w > 0 ? wsum[w - 1] : 0);
    int start = incl - pl;
    g_astart[t] = start;
    g_len[t]    = c;
    cur[t]      = start;
    __syncthreads();

#pragma unroll
    for (int i = 0; i < INPUT_DIM / EMB; i++) {
        int j = i * EMB + t;
        unsigned cb = g_comb[j];
        int pos = atomicAdd(&cur[cb & (EMB - 1)], 1);
        g_pos[j] = (unsigned short)(pos | (cb & 0x8000u));
    }
}

// ---------------- K3: persistent pipelined gather ----------------
#define GTHREADS 512
#define GRID_G   296                       // 2 CTAs/SM x 148 SMs, single wave

__global__ __launch_bounds__(GTHREADS, 2)
void k_gather(const float* __restrict__ x, float* __restrict__ out) {
    extern __shared__ float xs[];          // [XS_N]
    int t = threadIdx.x;

    // per-CTA-invariant: bucket metadata + full pos permutation in registers
    int s0a = __ldg(&g_astart[t]);
    int la  = __ldg(&g_len[t]);
    int s0b = __ldg(&g_astart[t + GTHREADS]);
    int lb  = __ldg(&g_len[t + GTHREADS]);

    uint2 q[8];
    {
        const uint2* gp = reinterpret_cast<const uint2*>(g_pos);
#pragma unroll
        for (int i = 0; i < 8; i++) q[i] = gp[t + i * GTHREADS];
    }

    // zero pad slots ONCE (scatter never writes pads; reused every row)
    {
        int pa = (la + 3) & ~3;
        for (int k = s0a + la; k < s0a + pa; k++) xs[k] = 0.0f;
        int pb = (lb + 3) & ~3;
        for (int k = s0b + lb; k < s0b + pb; k++) xs[k] = 0.0f;
    }

    int n4a = ((la + 3) & ~3) >> 2;
    int n4b = ((lb + 3) & ~3) >> 2;

    // prefetch first row
    int b = blockIdx.x;
    float4 v[8];
    if (b < BATCH) {
        const float4* gx = reinterpret_cast<const float4*>(x + (size_t)b * INPUT_DIM);
#pragma unroll
        for (int i = 0; i < 8; i++) v[i] = gx[t + i * GTHREADS];
    }

    for (; b < BATCH; b += GRID_G) {
        __syncthreads();                   // previous Phase C finished reading xs

        // scatter current row from registers (sign-applied)
#pragma unroll
        for (int i = 0; i < 8; i++) {
            unsigned q0 = q[i].x & 0xFFFFu, q1 = q[i].x >> 16;
            unsigned q2 = q[i].y & 0xFFFFu, q3 = q[i].y >> 16;
            xs[q0 & 0x7FFFu] = __uint_as_float(__float_as_uint(v[i].x) ^ ((q0 & 0x8000u) << 16));
            xs[q1 & 0x7FFFu] = __uint_as_float(__float_as_uint(v[i].y) ^ ((q1 & 0x8000u) << 16));
            xs[q2 & 0x7FFFu] = __uint_as_float(__float_as_uint(v[i].z) ^ ((q2 & 0x8000u) << 16));
            xs[q3 & 0x7FFFu] = __uint_as_float(__float_as_uint(v[i].w) ^ ((q3 & 0x8000u) << 16));
        }

        // issue next row's loads NOW — DRAM streams during barrier + Phase C
        int bn = b + GRID_G;
        if (bn < BATCH) {
            const float4* gx = reinterpret_cast<const float4*>(x + (size_t)bn * INPUT_DIM);
#pragma unroll
            for (int i = 0; i < 8; i++) v[i] = gx[t + i * GTHREADS];
        }

        __syncthreads();                   // scatter visible

        // Phase C: contiguous float4 reduction, buckets t and t+512
        float* o = out + (size_t)b * EMB;
        {
            const float4* xs4 = reinterpret_cast<const float4*>(xs) + (s0a >> 2);
            float acc = 0.0f;
            for (int i = 0; i < n4a; i++) {
                float4 u = xs4[i];
                acc += (u.x + u.y) + (u.z + u.w);
            }
            o[t] = acc;
        }
        {
            const float4* xs4 = reinterpret_cast<const float4*>(xs) + (s0b >> 2);
            float acc = 0.0f;
            for (int i = 0; i < n4b; i++) {
                float4 u = xs4[i];
                acc += (u.x + u.y) + (u.z + u.w);
            }
            o[t + GTHREADS] = acc;
        }
    }
}

extern "C" void kernel_launch(void* const* d_in, const int* in_sizes, int n_in,
                              void* d_out, int out_size) {
    const float* x  = (const float*)d_in[0];   // [BATCH, INPUT_DIM]
    const float* hp = (const float*)d_in[1];   // [INPUT_DIM, EMB]
    float* out = (float*)d_out;                // [BATCH, EMB]

    int smem = XS_N * (int)sizeof(float);      // 77824 B -> 2 blocks/SM
    cudaFuncSetAttribute(k_gather, cudaFuncAttributeMaxDynamicSharedMemorySize, smem);

    k_extract<<<(INPUT_DIM * 32) / 256, 256>>>(hp);
    k_build<<<1, EMB>>>();
    k_gather<<<GRID_G, GTHREADS, smem>>>(x, out);
}